// round 7
// baseline (speedup 1.0000x reference)
#include <cuda_runtime.h>
#include <cuda_fp16.h>
#include <cstdint>

#define NN 2048
#define EMBD 16
#define BB 64
#define CC 64

// Scratch (no cudaMalloc allowed)
static __device__ __half g_A[NN * NN];            // adjacency, fp16
static __device__ __half g_XT[BB * CC * NN];      // X^T [b][c][m], fp16
static __device__ float  g_y1[BB * NN * CC];      // A@X (fp32)
static __device__ __half g_y1T[BB * CC * NN];     // y1^T [b][c][m], fp16
static __device__ float  g_y2[BB * NN * CC];      // 2A@y1 - X (fp32)
static __device__ __half g_WT[NN * 3 * CC * CC];  // per-node weights [n][o][kk], fp16

// ---------------------------------------------------------------------------
__device__ __forceinline__ uint32_t smem_u32(const void* p) {
    uint32_t a;
    asm("{ .reg .u64 t; cvta.to.shared.u64 t, %1; cvt.u32.u64 %0, t; }" : "=r"(a) : "l"(p));
    return a;
}
__device__ __forceinline__ void cp16(uint32_t dst, const void* src) {
    asm volatile("cp.async.cg.shared.global [%0], [%1], 16;" :: "r"(dst), "l"(src));
}
__device__ __forceinline__ void cp_commit() { asm volatile("cp.async.commit_group;"); }
__device__ __forceinline__ void cp_wait2() { asm volatile("cp.async.wait_group 2;" ::: "memory"); }

// fp16 mma: D(f32) += A(f16) * B(f16),  m16n8k16
__device__ __forceinline__ void mma16(float* d, const uint32_t* a, uint32_t b0, uint32_t b1) {
    asm volatile(
        "mma.sync.aligned.m16n8k16.row.col.f32.f16.f16.f32 "
        "{%0,%1,%2,%3}, {%4,%5,%6,%7}, {%8,%9}, {%0,%1,%2,%3};"
        : "+f"(d[0]), "+f"(d[1]), "+f"(d[2]), "+f"(d[3])
        : "r"(a[0]), "r"(a[1]), "r"(a[2]), "r"(a[3]), "r"(b0), "r"(b1));
}
__device__ __forceinline__ void ldsm4(uint32_t* r, uint32_t addr) {
    asm volatile("ldmatrix.sync.aligned.m8n8.x4.shared.b16 {%0,%1,%2,%3}, [%4];"
                 : "=r"(r[0]), "=r"(r[1]), "=r"(r[2]), "=r"(r[3]) : "r"(addr));
}

// ---------------------------------------------------------------------------
// K0: A[row,:] = fp16(softmax(relu(E[row] . E[j])))
// ---------------------------------------------------------------------------
__global__ __launch_bounds__(256) void supports_kernel(const float* __restrict__ E,
                                                       __half* __restrict__ A) {
    __shared__ float z[NN];
    __shared__ float red[8];
    __shared__ float en[EMBD];
    int row = blockIdx.x;
    int tid = threadIdx.x;
    if (tid < EMBD) en[tid] = E[row * EMBD + tid];
    __syncthreads();
    float er[EMBD];
#pragma unroll
    for (int d = 0; d < EMBD; d++) er[d] = en[d];

    float lmax = 0.f;
    for (int j = tid; j < NN; j += 256) {
        const float4* ej = reinterpret_cast<const float4*>(E + (size_t)j * EMBD);
        float s = 0.f;
#pragma unroll
        for (int q = 0; q < 4; q++) {
            float4 v = ej[q];
            s = fmaf(er[q * 4 + 0], v.x, s);
            s = fmaf(er[q * 4 + 1], v.y, s);
            s = fmaf(er[q * 4 + 2], v.z, s);
            s = fmaf(er[q * 4 + 3], v.w, s);
        }
        s = fmaxf(s, 0.f);
        z[j] = s;
        lmax = fmaxf(lmax, s);
    }
#pragma unroll
    for (int o = 16; o > 0; o >>= 1) lmax = fmaxf(lmax, __shfl_xor_sync(~0u, lmax, o));
    if ((tid & 31) == 0) red[tid >> 5] = lmax;
    __syncthreads();
    float bmax = red[0];
#pragma unroll
    for (int w = 1; w < 8; w++) bmax = fmaxf(bmax, red[w]);
    __syncthreads();

    float lsum = 0.f;
    for (int j = tid; j < NN; j += 256) {
        float e = __expf(z[j] - bmax);
        z[j] = e;
        lsum += e;
    }
#pragma unroll
    for (int o = 16; o > 0; o >>= 1) lsum += __shfl_xor_sync(~0u, lsum, o);
    if ((tid & 31) == 0) red[tid >> 5] = lsum;
    __syncthreads();
    float bsum = 0.f;
#pragma unroll
    for (int w = 0; w < 8; w++) bsum += red[w];
    float inv = 1.f / bsum;
    for (int j = tid; j < NN; j += 256) A[(size_t)row * NN + j] = __float2half_rn(z[j] * inv);
}

// ---------------------------------------------------------------------------
// Transpose per b: D[b][c][m] = fp16(S[b][m][c]). 32x32 tiles.
// ---------------------------------------------------------------------------
__global__ __launch_bounds__(256) void trh_kernel(const float* __restrict__ S,
                                                  __half* __restrict__ D) {
    __shared__ float Ts[32][33];
    int m0 = blockIdx.x * 32;
    int c0 = blockIdx.y * 32;
    int b = blockIdx.z;
    int tid = threadIdx.x;
    int r = tid >> 3, q = tid & 7;
    float4 v = *reinterpret_cast<const float4*>(S + ((size_t)b * NN + m0 + r) * CC + c0 + q * 4);
    Ts[r][q * 4 + 0] = v.x;
    Ts[r][q * 4 + 1] = v.y;
    Ts[r][q * 4 + 2] = v.z;
    Ts[r][q * 4 + 3] = v.w;
    __syncthreads();
    __half2 p0 = __halves2half2(__float2half_rn(Ts[q * 4 + 0][r]),
                                __float2half_rn(Ts[q * 4 + 1][r]));
    __half2 p1 = __halves2half2(__float2half_rn(Ts[q * 4 + 2][r]),
                                __float2half_rn(Ts[q * 4 + 3][r]));
    __half2* dptr = reinterpret_cast<__half2*>(D + ((size_t)b * CC + c0 + r) * NN + m0 + q * 4);
    dptr[0] = p0;
    dptr[1] = p1;
}

// ---------------------------------------------------------------------------
// W precompute (transposed, fp16): WT[n][o*192 + kk] = fp16(sum_d E[n,d]*wp[d, kk*64+o])
// ---------------------------------------------------------------------------
__global__ __launch_bounds__(256) void wpre_kernel(const float* __restrict__ E,
                                                   const float* __restrict__ wp,
                                                   __half* __restrict__ WT) {
    __shared__ float wps[EMBD][256];
    __shared__ float Es[32][EMBD];
    int k0 = blockIdx.x * 4;
    int idx0 = blockIdx.x * 256;
    int n0 = blockIdx.y * 32;
    int tid = threadIdx.x;
#pragma unroll
    for (int i = 0; i < 4; i++) {
        int f = tid + i * 256;
        int d = f >> 6, c4 = f & 63;
        float4 v = *reinterpret_cast<const float4*>(wp + (size_t)d * 12288 + idx0 + c4 * 4);
        *reinterpret_cast<float4*>(&wps[d][c4 * 4]) = v;
    }
    if (tid < 128) {
        int nl = tid >> 2, dq = tid & 3;
        float4 v = *reinterpret_cast<const float4*>(E + (n0 + nl) * EMBD + dq * 4);
        *reinterpret_cast<float4*>(&Es[nl][dq * 4]) = v;
    }
    __syncthreads();

    int o = tid & 63;
    int g = tid >> 6;
    float wc[4][EMBD];
#pragma unroll
    for (int dk = 0; dk < 4; dk++)
#pragma unroll
        for (int d = 0; d < EMBD; d++) wc[dk][d] = wps[d][dk * 64 + o];

#pragma unroll
    for (int q = 0; q < 8; q++) {
        int nl = g * 8 + q;
        float s[4] = {0.f, 0.f, 0.f, 0.f};
#pragma unroll
        for (int d = 0; d < EMBD; d++) {
            float e = Es[nl][d];
#pragma unroll
            for (int dk = 0; dk < 4; dk++) s[dk] = fmaf(e, wc[dk][d], s[dk]);
        }
        __half2 h01 = __halves2half2(__float2half_rn(s[0]), __float2half_rn(s[1]));
        __half2 h23 = __halves2half2(__float2half_rn(s[2]), __float2half_rn(s[3]));
        __half2* dst = reinterpret_cast<__half2*>(
            WT + (size_t)(n0 + nl) * 12288 + o * 192 + k0);
        dst[0] = h01;
        dst[1] = h23;
    }
}

// ---------------------------------------------------------------------------
// fp16 mma.sync GEMM: CTA 128x128xK32, 8 warps (2m x 4n), warp tile 64x32.
// 4-stage cp.async pipeline, fp16 operands (64B rows, XOR swizzle), fp32 acc.
// D[n, bc] = sum_m A[n,m] * Bt[bc, m].  mode 1: Y=acc. mode 2: Y=2*acc-Xsub.
// ---------------------------------------------------------------------------
#define GEMM_SMEM 65536  // 4 stages x (A 8KB + B 8KB)

__global__ __launch_bounds__(256, 2) void mma_gemm(const __half* __restrict__ Ag,
                                                   const __half* __restrict__ Bt,
                                                   float* __restrict__ Y,
                                                   const float* __restrict__ Xsub,
                                                   int mode) {
    extern __shared__ char smc[];
    uint32_t sb = smem_u32(smc);

    int tid = threadIdx.x;
    int wid = tid >> 5;
    int lid = tid & 31;
    int wm = wid & 1;   // m offset *64
    int wn = wid >> 1;  // n offset *32
    int n0 = blockIdx.x * 128;
    int bc0 = blockIdx.y * 128;

    const __half* Arow = Ag + (size_t)n0 * NN;
    const __half* Brow = Bt + (size_t)bc0 * NN;

    auto load_tile = [&](int it, int buf) {
        int m0 = it * 32;
        uint32_t ab = sb + buf * 16384;
        uint32_t bb = ab + 8192;
#pragma unroll
        for (int i = 0; i < 2; i++) {
            int idx = tid + i * 256;
            int row = idx >> 2, c = idx & 3;
            int pc = c ^ ((row >> 1) & 3);
            cp16(ab + row * 64 + pc * 16, Arow + (size_t)row * NN + m0 + c * 8);
        }
#pragma unroll
        for (int i = 0; i < 2; i++) {
            int idx = tid + i * 256;
            int row = idx >> 2, c = idx & 3;
            int pc = c ^ ((row >> 1) & 3);
            cp16(bb + row * 64 + pc * 16, Brow + (size_t)row * NN + m0 + c * 8);
        }
        cp_commit();
    };

    int lm = lid >> 3, lrw = lid & 7;
    int xorv = (lrw >> 1) & 3;
    int chHalf = lm >> 1;
    uint32_t aBase = (uint32_t)(wm * 64 + (lm & 1) * 8 + lrw) * 64;
    uint32_t bBase = (uint32_t)(wn * 32 + (lm & 1) * 8 + lrw) * 64;

    float acc[4][4][4];
#pragma unroll
    for (int mt = 0; mt < 4; mt++)
#pragma unroll
        for (int nt = 0; nt < 4; nt++)
#pragma unroll
            for (int q = 0; q < 4; q++) acc[mt][nt][q] = 0.f;

    load_tile(0, 0);
    load_tile(1, 1);
    load_tile(2, 2);

    const int ITERS = NN / 32;
    for (int it = 0; it < ITERS; it++) {
        int buf = it & 3;
        cp_wait2();
        __syncthreads();
        uint32_t aB = sb + buf * 16384 + aBase;
        uint32_t bB = sb + buf * 16384 + 8192 + bBase;

        uint32_t af[4][4], bf[2][4];
        {
            uint32_t pc = (uint32_t)((0 + chHalf) ^ xorv) * 16;
#pragma unroll
            for (int mt = 0; mt < 4; mt++) ldsm4(af[mt], aB + mt * 1024 + pc);
#pragma unroll
            for (int g = 0; g < 2; g++) ldsm4(bf[g], bB + g * 1024 + pc);
        }
        if (it + 3 < ITERS) load_tile(it + 3, (it + 3) & 3); else cp_commit();
#pragma unroll
        for (int mt = 0; mt < 4; mt++)
#pragma unroll
            for (int g = 0; g < 2; g++) {
                mma16(acc[mt][g * 2 + 0], af[mt], bf[g][0], bf[g][2]);
                mma16(acc[mt][g * 2 + 1], af[mt], bf[g][1], bf[g][3]);
            }
        {
            uint32_t pc = (uint32_t)((2 + chHalf) ^ xorv) * 16;
#pragma unroll
            for (int mt = 0; mt < 4; mt++) ldsm4(af[mt], aB + mt * 1024 + pc);
#pragma unroll
            for (int g = 0; g < 2; g++) ldsm4(bf[g], bB + g * 1024 + pc);
        }
#pragma unroll
        for (int mt = 0; mt < 4; mt++)
#pragma unroll
            for (int g = 0; g < 2; g++) {
                mma16(acc[mt][g * 2 + 0], af[mt], bf[g][0], bf[g][2]);
                mma16(acc[mt][g * 2 + 1], af[mt], bf[g][1], bf[g][3]);
            }
    }

    int lr = lid >> 2, lc = lid & 3;
#pragma unroll
    for (int mt = 0; mt < 4; mt++) {
#pragma unroll
        for (int nt = 0; nt < 4; nt++) {
            int n = n0 + wm * 64 + mt * 16 + lr;
            int bc = bc0 + wn * 32 + (nt >> 1) * 16 + (nt & 1) * 8 + lc * 2;
            int b = bc >> 6, c = bc & 63;
            float2 v0 = make_float2(acc[mt][nt][0], acc[mt][nt][1]);
            float2 v1 = make_float2(acc[mt][nt][2], acc[mt][nt][3]);
            if (mode == 2) {
                const float2 x0 = *reinterpret_cast<const float2*>(
                    Xsub + ((size_t)b * NN + n) * CC + c);
                const float2 x1 = *reinterpret_cast<const float2*>(
                    Xsub + ((size_t)b * NN + n + 8) * CC + c);
                v0.x = fmaf(2.f, v0.x, -x0.x);
                v0.y = fmaf(2.f, v0.y, -x0.y);
                v1.x = fmaf(2.f, v1.x, -x1.x);
                v1.y = fmaf(2.f, v1.y, -x1.y);
            }
            *reinterpret_cast<float2*>(Y + ((size_t)b * NN + n) * CC + c) = v0;
            *reinterpret_cast<float2*>(Y + ((size_t)b * NN + n + 8) * CC + c) = v1;
        }
    }
}

// ---------------------------------------------------------------------------
// out4: per-node fp16 tensor-core contraction. One block (128 thr, 4 warps) per n.
//   D[64 b, 64 o] = XG[64 b, 192 kk] @ WT[64 o, 192 kk]^T  + bias (fp32)
// Smem rows: 200 halfs (400 B; 400 mod 128 = 16 -> conflict-free ldmatrix).
// ---------------------------------------------------------------------------
#define HSTR 200
#define OUT4_SMEM ((64 * HSTR * 2) * 2 + 64 * 4)
__global__ __launch_bounds__(128) void out4_kernel(const float* __restrict__ X,
                                                   const float* __restrict__ E,
                                                   const __half* __restrict__ WTg,
                                                   const float* __restrict__ bp,
                                                   float* __restrict__ OUT) {
    extern __shared__ char smc[];
    __half* XGs = reinterpret_cast<__half*>(smc);            // 64 * 200 halfs
    __half* WTs = XGs + 64 * HSTR;                           // 64 * 200 halfs
    float* bs = reinterpret_cast<float*>(smc + 64 * HSTR * 2 * 2);  // 64 floats
    __shared__ float en[EMBD];

    int n = blockIdx.x;
    int tid = threadIdx.x;
    int wid = tid >> 5;
    int lid = tid & 31;
    if (tid < EMBD) en[tid] = E[n * EMBD + tid];
    __syncthreads();

    // XG staging fp16: XGs[b*HSTR + k*64 + i]
    const float* srcs[3] = {X, g_y1, g_y2};
#pragma unroll
    for (int k = 0; k < 3; k++) {
        const float* src = srcs[k];
#pragma unroll
        for (int rep = 0; rep < 32; rep++) {
            int idx = tid + rep * 128;
            int b = idx >> 6, i = idx & 63;
            XGs[b * HSTR + k * 64 + i] = __float2half_rn(src[((size_t)b * NN + n) * CC + i]);
        }
    }
    // WT[n]: 12288 halfs, remap stride 192 -> 200 (8-half chunks stay within one o)
    {
        const uint4* src = reinterpret_cast<const uint4*>(WTg + (size_t)n * 12288);
#pragma unroll
        for (int rep = 0; rep < 12; rep++) {
            int c8 = tid + rep * 128;        // 0..1535 chunks of 8 halfs
            int idx = c8 * 8;
            int o = idx / 192, kk = idx - o * 192;
            *reinterpret_cast<uint4*>(&WTs[o * HSTR + kk]) = src[c8];
        }
    }
    if (tid < 64) {
        float s = 0.f;
#pragma unroll
        for (int d = 0; d < EMBD; d++) s = fmaf(en[d], bp[d * 64 + tid], s);
        bs[tid] = s;
    }
    __syncthreads();

    int lm = lid >> 3, lrw = lid & 7;
    uint32_t aLane = smem_u32(XGs) + (uint32_t)(wid * 16 + (lm & 1) * 8 + lrw) * (HSTR * 2) +
                     (lm >> 1) * 16;
    uint32_t bLane = smem_u32(WTs) + (uint32_t)((lm & 1) * 8 + lrw) * (HSTR * 2) +
                     (lm >> 1) * 16;

    float acc[8][4];
#pragma unroll
    for (int nt = 0; nt < 8; nt++)
#pragma unroll
        for (int q = 0; q < 4; q++) acc[nt][q] = 0.f;

#pragma unroll
    for (int kt = 0; kt < 12; kt++) {
        uint32_t koff = (uint32_t)kt * 32;
        uint32_t af[4];
        ldsm4(af, aLane + koff);
#pragma unroll
        for (int g = 0; g < 4; g++) {
            uint32_t bf[4];
            ldsm4(bf, bLane + g * 16 * (HSTR * 2) + koff);
            mma16(acc[g * 2 + 0], af, bf[0], bf[2]);
            mma16(acc[g * 2 + 1], af, bf[1], bf[3]);
        }
    }

    int lr = lid >> 2, lc = lid & 3;
    int b0 = wid * 16 + lr;
#pragma unroll
    for (int nt = 0; nt < 8; nt++) {
        int o = nt * 8 + lc * 2;
        float2 bias = *reinterpret_cast<const float2*>(&bs[o]);
        float2 v0 = make_float2(acc[nt][0] + bias.x, acc[nt][1] + bias.y);
        float2 v1 = make_float2(acc[nt][2] + bias.x, acc[nt][3] + bias.y);
        *reinterpret_cast<float2*>(OUT + ((size_t)b0 * NN + n) * CC + o) = v0;
        *reinterpret_cast<float2*>(OUT + ((size_t)(b0 + 8) * NN + n) * CC + o) = v1;
    }
}

// ---------------------------------------------------------------------------
extern "C" void kernel_launch(void* const* d_in, const int* in_sizes, int n_in,
                              void* d_out, int out_size) {
    const float *x = nullptr, *E = nullptr, *wp = nullptr, *bp = nullptr;
    for (int i = 0; i < n_in; i++) {
        switch (in_sizes[i]) {
            case BB * NN * CC:       x = (const float*)d_in[i]; break;
            case NN * EMBD:          E = (const float*)d_in[i]; break;
            case EMBD * 3 * CC * CC: wp = (const float*)d_in[i]; break;
            case EMBD * CC:          bp = (const float*)d_in[i]; break;
        }
    }
    float* out = (float*)d_out;

    __half *A, *XT, *y1T, *WT;
    float *y1, *y2;
    cudaGetSymbolAddress((void**)&A, g_A);
    cudaGetSymbolAddress((void**)&XT, g_XT);
    cudaGetSymbolAddress((void**)&y1, g_y1);
    cudaGetSymbolAddress((void**)&y1T, g_y1T);
    cudaGetSymbolAddress((void**)&y2, g_y2);
    cudaGetSymbolAddress((void**)&WT, g_WT);

    supports_kernel<<<NN, 256>>>(E, A);
    trh_kernel<<<dim3(NN / 32, CC / 32, BB), 256>>>(x, XT);
    wpre_kernel<<<dim3(48, 64), 256>>>(E, wp, WT);

    cudaFuncSetAttribute(mma_gemm, cudaFuncAttributeMaxDynamicSharedMemorySize, GEMM_SMEM);
    dim3 ggrid(NN / 128, (BB * CC) / 128);
    mma_gemm<<<ggrid, 256, GEMM_SMEM>>>(A, XT, y1, nullptr, 1);
    trh_kernel<<<dim3(NN / 32, CC / 32, BB), 256>>>(y1, y1T);
    mma_gemm<<<ggrid, 256, GEMM_SMEM>>>(A, y1T, y2, x, 2);

    cudaFuncSetAttribute(out4_kernel, cudaFuncAttributeMaxDynamicSharedMemorySize, OUT4_SMEM);
    out4_kernel<<<NN, 128, OUT4_SMEM>>>(x, E, WT, bp, out);
}

// round 8
// speedup vs baseline: 1.0660x; 1.0660x over previous
#include <cuda_runtime.h>
#include <cuda_fp16.h>
#include <cstdint>

#define NN 2048
#define EMBD 16
#define BB 64
#define CC 64

// Scratch (no cudaMalloc allowed)
static __device__ __half g_A[NN * NN];            // adjacency, fp16
static __device__ __half g_XT[BB * CC * NN];      // X^T [b][c][m], fp16
static __device__ __half g_y1h[BB * NN * CC];     // A@X, fp16, [b][n][c]
static __device__ __half g_y1T[BB * CC * NN];     // y1^T [b][c][m], fp16
static __device__ __half g_y2h[BB * NN * CC];     // 2A@y1 - X, fp16, [b][n][c]
static __device__ __half g_WT[NN * 3 * CC * CC];  // per-node weights [n][o][kk], fp16

// ---------------------------------------------------------------------------
__device__ __forceinline__ uint32_t smem_u32(const void* p) {
    uint32_t a;
    asm("{ .reg .u64 t; cvta.to.shared.u64 t, %1; cvt.u32.u64 %0, t; }" : "=r"(a) : "l"(p));
    return a;
}
__device__ __forceinline__ void cp16(uint32_t dst, const void* src) {
    asm volatile("cp.async.cg.shared.global [%0], [%1], 16;" :: "r"(dst), "l"(src));
}
__device__ __forceinline__ void cp_commit() { asm volatile("cp.async.commit_group;"); }
__device__ __forceinline__ void cp_wait2() { asm volatile("cp.async.wait_group 2;" ::: "memory"); }

__device__ __forceinline__ void mma16(float* d, const uint32_t* a, uint32_t b0, uint32_t b1) {
    asm volatile(
        "mma.sync.aligned.m16n8k16.row.col.f32.f16.f16.f32 "
        "{%0,%1,%2,%3}, {%4,%5,%6,%7}, {%8,%9}, {%0,%1,%2,%3};"
        : "+f"(d[0]), "+f"(d[1]), "+f"(d[2]), "+f"(d[3])
        : "r"(a[0]), "r"(a[1]), "r"(a[2]), "r"(a[3]), "r"(b0), "r"(b1));
}
__device__ __forceinline__ void ldsm4(uint32_t* r, uint32_t addr) {
    asm volatile("ldmatrix.sync.aligned.m8n8.x4.shared.b16 {%0,%1,%2,%3}, [%4];"
                 : "=r"(r[0]), "=r"(r[1]), "=r"(r[2]), "=r"(r[3]) : "r"(addr));
}

// ---------------------------------------------------------------------------
// K0: A[r,:] = fp16(softmax(relu(E[r] . E[j]))), 4 rows per block (E reuse).
// No max-subtraction: relu dots are small (<~40), exp() safe in fp32.
// ---------------------------------------------------------------------------
#define SR 4
__global__ __launch_bounds__(256) void supports_kernel(const float* __restrict__ E,
                                                       __half* __restrict__ A) {
    extern __shared__ float zs[];               // SR * NN
    __shared__ float red[SR][8];
    __shared__ float en[SR][EMBD];
    int row0 = blockIdx.x * SR;
    int tid = threadIdx.x;
    if (tid < SR * EMBD) en[tid >> 4][tid & 15] = E[row0 * EMBD + tid];
    __syncthreads();

    float er[SR][EMBD];
#pragma unroll
    for (int r = 0; r < SR; r++)
#pragma unroll
        for (int d = 0; d < EMBD; d++) er[r][d] = en[r][d];

    float lsum[SR] = {0.f, 0.f, 0.f, 0.f};
    for (int j = tid; j < NN; j += 256) {
        const float4* ej = reinterpret_cast<const float4*>(E + (size_t)j * EMBD);
        float4 v0 = ej[0], v1 = ej[1], v2 = ej[2], v3 = ej[3];
#pragma unroll
        for (int r = 0; r < SR; r++) {
            float s = 0.f;
            s = fmaf(er[r][0], v0.x, s);  s = fmaf(er[r][1], v0.y, s);
            s = fmaf(er[r][2], v0.z, s);  s = fmaf(er[r][3], v0.w, s);
            s = fmaf(er[r][4], v1.x, s);  s = fmaf(er[r][5], v1.y, s);
            s = fmaf(er[r][6], v1.z, s);  s = fmaf(er[r][7], v1.w, s);
            s = fmaf(er[r][8], v2.x, s);  s = fmaf(er[r][9], v2.y, s);
            s = fmaf(er[r][10], v2.z, s); s = fmaf(er[r][11], v2.w, s);
            s = fmaf(er[r][12], v3.x, s); s = fmaf(er[r][13], v3.y, s);
            s = fmaf(er[r][14], v3.z, s); s = fmaf(er[r][15], v3.w, s);
            float e = __expf(fmaxf(s, 0.f));
            zs[r * NN + j] = e;
            lsum[r] += e;
        }
    }
#pragma unroll
    for (int r = 0; r < SR; r++) {
#pragma unroll
        for (int o = 16; o > 0; o >>= 1) lsum[r] += __shfl_xor_sync(~0u, lsum[r], o);
        if ((tid & 31) == 0) red[r][tid >> 5] = lsum[r];
    }
    __syncthreads();
    float inv[SR];
#pragma unroll
    for (int r = 0; r < SR; r++) {
        float s = 0.f;
#pragma unroll
        for (int w = 0; w < 8; w++) s += red[r][w];
        inv[r] = 1.f / s;
    }
    for (int j = tid; j < NN; j += 256) {
#pragma unroll
        for (int r = 0; r < SR; r++)
            A[(size_t)(row0 + r) * NN + j] = __float2half_rn(zs[r * NN + j] * inv[r]);
    }
}

// ---------------------------------------------------------------------------
// Transpose per b (fp32 -> fp16): D[b][c][m] = fp16(S[b][m][c]). 32x32 tiles.
// ---------------------------------------------------------------------------
__global__ __launch_bounds__(256) void trh_kernel(const float* __restrict__ S,
                                                  __half* __restrict__ D) {
    __shared__ float Ts[32][33];
    int m0 = blockIdx.x * 32;
    int c0 = blockIdx.y * 32;
    int b = blockIdx.z;
    int tid = threadIdx.x;
    int r = tid >> 3, q = tid & 7;
    float4 v = *reinterpret_cast<const float4*>(S + ((size_t)b * NN + m0 + r) * CC + c0 + q * 4);
    Ts[r][q * 4 + 0] = v.x;
    Ts[r][q * 4 + 1] = v.y;
    Ts[r][q * 4 + 2] = v.z;
    Ts[r][q * 4 + 3] = v.w;
    __syncthreads();
    __half2 p0 = __halves2half2(__float2half_rn(Ts[q * 4 + 0][r]),
                                __float2half_rn(Ts[q * 4 + 1][r]));
    __half2 p1 = __halves2half2(__float2half_rn(Ts[q * 4 + 2][r]),
                                __float2half_rn(Ts[q * 4 + 3][r]));
    __half2* dptr = reinterpret_cast<__half2*>(D + ((size_t)b * CC + c0 + r) * NN + m0 + q * 4);
    dptr[0] = p0;
    dptr[1] = p1;
}

// ---------------------------------------------------------------------------
// Transpose per b (fp16 -> fp16): D[b][c][m] = S[b][m][c]. 32x32 tiles.
// ---------------------------------------------------------------------------
__global__ __launch_bounds__(256) void trhh_kernel(const __half* __restrict__ S,
                                                   __half* __restrict__ D) {
    __shared__ __half Ts[32][40];
    int m0 = blockIdx.x * 32;
    int c0 = blockIdx.y * 32;
    int b = blockIdx.z;
    int tid = threadIdx.x;
    int r = tid >> 3, q = tid & 7;
    union { uint2 u; __half h[4]; } in;
    in.u = *reinterpret_cast<const uint2*>(S + ((size_t)b * NN + m0 + r) * CC + c0 + q * 4);
#pragma unroll
    for (int j = 0; j < 4; j++) Ts[r][q * 4 + j] = in.h[j];
    __syncthreads();
    union { uint2 u; __half h[4]; } out;
#pragma unroll
    for (int j = 0; j < 4; j++) out.h[j] = Ts[q * 4 + j][r];
    *reinterpret_cast<uint2*>(D + ((size_t)b * CC + c0 + r) * NN + m0 + q * 4) = out.u;
}

// ---------------------------------------------------------------------------
// W precompute (transposed, fp16): WT[n][o*192 + kk] = fp16(sum_d E[n,d]*wp[d, kk*64+o])
// ---------------------------------------------------------------------------
__global__ __launch_bounds__(256) void wpre_kernel(const float* __restrict__ E,
                                                   const float* __restrict__ wp,
                                                   __half* __restrict__ WT) {
    __shared__ float wps[EMBD][256];
    __shared__ float Es[32][EMBD];
    int k0 = blockIdx.x * 4;
    int idx0 = blockIdx.x * 256;
    int n0 = blockIdx.y * 32;
    int tid = threadIdx.x;
#pragma unroll
    for (int i = 0; i < 4; i++) {
        int f = tid + i * 256;
        int d = f >> 6, c4 = f & 63;
        float4 v = *reinterpret_cast<const float4*>(wp + (size_t)d * 12288 + idx0 + c4 * 4);
        *reinterpret_cast<float4*>(&wps[d][c4 * 4]) = v;
    }
    if (tid < 128) {
        int nl = tid >> 2, dq = tid & 3;
        float4 v = *reinterpret_cast<const float4*>(E + (n0 + nl) * EMBD + dq * 4);
        *reinterpret_cast<float4*>(&Es[nl][dq * 4]) = v;
    }
    __syncthreads();

    int o = tid & 63;
    int g = tid >> 6;
    float wc[4][EMBD];
#pragma unroll
    for (int dk = 0; dk < 4; dk++)
#pragma unroll
        for (int d = 0; d < EMBD; d++) wc[dk][d] = wps[d][dk * 64 + o];

#pragma unroll
    for (int q = 0; q < 8; q++) {
        int nl = g * 8 + q;
        float s[4] = {0.f, 0.f, 0.f, 0.f};
#pragma unroll
        for (int d = 0; d < EMBD; d++) {
            float e = Es[nl][d];
#pragma unroll
            for (int dk = 0; dk < 4; dk++) s[dk] = fmaf(e, wc[dk][d], s[dk]);
        }
        __half2 h01 = __halves2half2(__float2half_rn(s[0]), __float2half_rn(s[1]));
        __half2 h23 = __halves2half2(__float2half_rn(s[2]), __float2half_rn(s[3]));
        __half2* dst = reinterpret_cast<__half2*>(
            WT + (size_t)(n0 + nl) * 12288 + o * 192 + k0);
        dst[0] = h01;
        dst[1] = h23;
    }
}

// ---------------------------------------------------------------------------
// fp16 mma.sync GEMM: CTA 128x128xK32, 8 warps (2m x 4n), warp tile 64x32.
// 4-stage cp.async pipeline, fp16 operands, fp32 acc, fp16 output.
// mode 1: Yh = acc.  mode 2: Yh = 2*acc - Xsub.
// ---------------------------------------------------------------------------
#define GEMM_SMEM 65536

__global__ __launch_bounds__(256, 2) void mma_gemm(const __half* __restrict__ Ag,
                                                   const __half* __restrict__ Bt,
                                                   __half* __restrict__ Yh,
                                                   const float* __restrict__ Xsub,
                                                   int mode) {
    extern __shared__ char smc[];
    uint32_t sb = smem_u32(smc);

    int tid = threadIdx.x;
    int wid = tid >> 5;
    int lid = tid & 31;
    int wm = wid & 1;
    int wn = wid >> 1;
    int n0 = blockIdx.x * 128;
    int bc0 = blockIdx.y * 128;

    const __half* Arow = Ag + (size_t)n0 * NN;
    const __half* Brow = Bt + (size_t)bc0 * NN;

    auto load_tile = [&](int it, int buf) {
        int m0 = it * 32;
        uint32_t ab = sb + buf * 16384;
        uint32_t bb = ab + 8192;
#pragma unroll
        for (int i = 0; i < 2; i++) {
            int idx = tid + i * 256;
            int row = idx >> 2, c = idx & 3;
            int pc = c ^ ((row >> 1) & 3);
            cp16(ab + row * 64 + pc * 16, Arow + (size_t)row * NN + m0 + c * 8);
        }
#pragma unroll
        for (int i = 0; i < 2; i++) {
            int idx = tid + i * 256;
            int row = idx >> 2, c = idx & 3;
            int pc = c ^ ((row >> 1) & 3);
            cp16(bb + row * 64 + pc * 16, Brow + (size_t)row * NN + m0 + c * 8);
        }
        cp_commit();
    };

    int lm = lid >> 3, lrw = lid & 7;
    int xorv = (lrw >> 1) & 3;
    int chHalf = lm >> 1;
    uint32_t aBase = (uint32_t)(wm * 64 + (lm & 1) * 8 + lrw) * 64;
    uint32_t bBase = (uint32_t)(wn * 32 + (lm & 1) * 8 + lrw) * 64;

    float acc[4][4][4];
#pragma unroll
    for (int mt = 0; mt < 4; mt++)
#pragma unroll
        for (int nt = 0; nt < 4; nt++)
#pragma unroll
            for (int q = 0; q < 4; q++) acc[mt][nt][q] = 0.f;

    load_tile(0, 0);
    load_tile(1, 1);
    load_tile(2, 2);

    const int ITERS = NN / 32;
    for (int it = 0; it < ITERS; it++) {
        int buf = it & 3;
        cp_wait2();
        __syncthreads();
        uint32_t aB = sb + buf * 16384 + aBase;
        uint32_t bB = sb + buf * 16384 + 8192 + bBase;

        uint32_t af[4][4], bf[2][4];
        {
            uint32_t pc = (uint32_t)((0 + chHalf) ^ xorv) * 16;
#pragma unroll
            for (int mt = 0; mt < 4; mt++) ldsm4(af[mt], aB + mt * 1024 + pc);
#pragma unroll
            for (int g = 0; g < 2; g++) ldsm4(bf[g], bB + g * 1024 + pc);
        }
        if (it + 3 < ITERS) load_tile(it + 3, (it + 3) & 3); else cp_commit();
#pragma unroll
        for (int mt = 0; mt < 4; mt++)
#pragma unroll
            for (int g = 0; g < 2; g++) {
                mma16(acc[mt][g * 2 + 0], af[mt], bf[g][0], bf[g][2]);
                mma16(acc[mt][g * 2 + 1], af[mt], bf[g][1], bf[g][3]);
            }
        {
            uint32_t pc = (uint32_t)((2 + chHalf) ^ xorv) * 16;
#pragma unroll
            for (int mt = 0; mt < 4; mt++) ldsm4(af[mt], aB + mt * 1024 + pc);
#pragma unroll
            for (int g = 0; g < 2; g++) ldsm4(bf[g], bB + g * 1024 + pc);
        }
#pragma unroll
        for (int mt = 0; mt < 4; mt++)
#pragma unroll
            for (int g = 0; g < 2; g++) {
                mma16(acc[mt][g * 2 + 0], af[mt], bf[g][0], bf[g][2]);
                mma16(acc[mt][g * 2 + 1], af[mt], bf[g][1], bf[g][3]);
            }
    }

    int lr = lid >> 2, lc = lid & 3;
#pragma unroll
    for (int mt = 0; mt < 4; mt++) {
#pragma unroll
        for (int nt = 0; nt < 4; nt++) {
            int n = n0 + wm * 64 + mt * 16 + lr;
            int bc = bc0 + wn * 32 + (nt >> 1) * 16 + (nt & 1) * 8 + lc * 2;
            int b = bc >> 6, c = bc & 63;
            float2 v0 = make_float2(acc[mt][nt][0], acc[mt][nt][1]);
            float2 v1 = make_float2(acc[mt][nt][2], acc[mt][nt][3]);
            if (mode == 2) {
                const float2 x0 = *reinterpret_cast<const float2*>(
                    Xsub + ((size_t)b * NN + n) * CC + c);
                const float2 x1 = *reinterpret_cast<const float2*>(
                    Xsub + ((size_t)b * NN + n + 8) * CC + c);
                v0.x = fmaf(2.f, v0.x, -x0.x);
                v0.y = fmaf(2.f, v0.y, -x0.y);
                v1.x = fmaf(2.f, v1.x, -x1.x);
                v1.y = fmaf(2.f, v1.y, -x1.y);
            }
            *reinterpret_cast<__half2*>(Yh + ((size_t)b * NN + n) * CC + c) =
                __floats2half2_rn(v0.x, v0.y);
            *reinterpret_cast<__half2*>(Yh + ((size_t)b * NN + n + 8) * CC + c) =
                __floats2half2_rn(v1.x, v1.y);
        }
    }
}

// ---------------------------------------------------------------------------
// out4: per-node fp16 tensor-core contraction. One block (128 thr, 4 warps) per n.
//   D[64 b, 64 o] = XG[64 b, 192 kk] @ WT[64 o, 192 kk]^T  + bias (fp32)
// ---------------------------------------------------------------------------
#define HSTR 200
#define OUT4_SMEM ((64 * HSTR * 2) * 2 + 64 * 4)
__global__ __launch_bounds__(128) void out4_kernel(const float* __restrict__ X,
                                                   const float* __restrict__ E,
                                                   const __half* __restrict__ WTg,
                                                   const float* __restrict__ bp,
                                                   float* __restrict__ OUT) {
    extern __shared__ char smc[];
    __half* XGs = reinterpret_cast<__half*>(smc);            // 64 * 200 halfs
    __half* WTs = XGs + 64 * HSTR;                           // 64 * 200 halfs
    float* bs = reinterpret_cast<float*>(smc + 64 * HSTR * 2 * 2);
    __shared__ float en[EMBD];

    int n = blockIdx.x;
    int tid = threadIdx.x;
    int wid = tid >> 5;
    int lid = tid & 31;
    if (tid < EMBD) en[tid] = E[n * EMBD + tid];
    __syncthreads();

    // XG k=0: x (fp32 -> fp16)
#pragma unroll
    for (int rep = 0; rep < 32; rep++) {
        int idx = tid + rep * 128;
        int b = idx >> 6, i = idx & 63;
        XGs[b * HSTR + i] = __float2half_rn(X[((size_t)b * NN + n) * CC + i]);
    }
    // XG k=1,2: y1h, y2h (fp16 pair copies)
    {
        const __half* s1 = g_y1h;
        const __half* s2 = g_y2h;
#pragma unroll
        for (int rep = 0; rep < 16; rep++) {
            int idx = tid + rep * 128;          // 0..2047 half2-pairs
            int b = idx >> 5, i2 = idx & 31;
            uint32_t v1 = *reinterpret_cast<const uint32_t*>(
                s1 + ((size_t)b * NN + n) * CC + i2 * 2);
            *reinterpret_cast<uint32_t*>(&XGs[b * HSTR + 64 + i2 * 2]) = v1;
            uint32_t v2 = *reinterpret_cast<const uint32_t*>(
                s2 + ((size_t)b * NN + n) * CC + i2 * 2);
            *reinterpret_cast<uint32_t*>(&XGs[b * HSTR + 128 + i2 * 2]) = v2;
        }
    }
    // WT[n]: 12288 halfs, remap stride 192 -> 200
    {
        const uint4* src = reinterpret_cast<const uint4*>(WTg + (size_t)n * 12288);
#pragma unroll
        for (int rep = 0; rep < 12; rep++) {
            int c8 = tid + rep * 128;
            int idx = c8 * 8;
            int o = idx / 192, kk = idx - o * 192;
            *reinterpret_cast<uint4*>(&WTs[o * HSTR + kk]) = src[c8];
        }
    }
    if (tid < 64) {
        float s = 0.f;
#pragma unroll
        for (int d = 0; d < EMBD; d++) s = fmaf(en[d], bp[d * 64 + tid], s);
        bs[tid] = s;
    }
    __syncthreads();

    int lm = lid >> 3, lrw = lid & 7;
    uint32_t aLane = smem_u32(XGs) + (uint32_t)(wid * 16 + (lm & 1) * 8 + lrw) * (HSTR * 2) +
                     (lm >> 1) * 16;
    uint32_t bLane = smem_u32(WTs) + (uint32_t)((lm & 1) * 8 + lrw) * (HSTR * 2) +
                     (lm >> 1) * 16;

    float acc[8][4];
#pragma unroll
    for (int nt = 0; nt < 8; nt++)
#pragma unroll
        for (int q = 0; q < 4; q++) acc[nt][q] = 0.f;

#pragma unroll
    for (int kt = 0; kt < 12; kt++) {
        uint32_t koff = (uint32_t)kt * 32;
        uint32_t af[4];
        ldsm4(af, aLane + koff);
#pragma unroll
        for (int g = 0; g < 4; g++) {
            uint32_t bf[4];
            ldsm4(bf, bLane + g * 16 * (HSTR * 2) + koff);
            mma16(acc[g * 2 + 0], af, bf[0], bf[2]);
            mma16(acc[g * 2 + 1], af, bf[1], bf[3]);
        }
    }

    int lr = lid >> 2, lc = lid & 3;
    int b0 = wid * 16 + lr;
#pragma unroll
    for (int nt = 0; nt < 8; nt++) {
        int o = nt * 8 + lc * 2;
        float2 bias = *reinterpret_cast<const float2*>(&bs[o]);
        float2 v0 = make_float2(acc[nt][0] + bias.x, acc[nt][1] + bias.y);
        float2 v1 = make_float2(acc[nt][2] + bias.x, acc[nt][3] + bias.y);
        *reinterpret_cast<float2*>(OUT + ((size_t)b0 * NN + n) * CC + o) = v0;
        *reinterpret_cast<float2*>(OUT + ((size_t)(b0 + 8) * NN + n) * CC + o) = v1;
    }
}

// ---------------------------------------------------------------------------
extern "C" void kernel_launch(void* const* d_in, const int* in_sizes, int n_in,
                              void* d_out, int out_size) {
    const float *x = nullptr, *E = nullptr, *wp = nullptr, *bp = nullptr;
    for (int i = 0; i < n_in; i++) {
        switch (in_sizes[i]) {
            case BB * NN * CC:       x = (const float*)d_in[i]; break;
            case NN * EMBD:          E = (const float*)d_in[i]; break;
            case EMBD * 3 * CC * CC: wp = (const float*)d_in[i]; break;
            case EMBD * CC:          bp = (const float*)d_in[i]; break;
        }
    }
    float* out = (float*)d_out;

    __half *A, *XT, *y1h, *y1T, *y2h, *WT;
    cudaGetSymbolAddress((void**)&A, g_A);
    cudaGetSymbolAddress((void**)&XT, g_XT);
    cudaGetSymbolAddress((void**)&y1h, g_y1h);
    cudaGetSymbolAddress((void**)&y1T, g_y1T);
    cudaGetSymbolAddress((void**)&y2h, g_y2h);
    cudaGetSymbolAddress((void**)&WT, g_WT);

    int ssm = SR * NN * (int)sizeof(float);
    cudaFuncSetAttribute(supports_kernel, cudaFuncAttributeMaxDynamicSharedMemorySize, ssm);
    supports_kernel<<<NN / SR, 256, ssm>>>(E, A);
    trh_kernel<<<dim3(NN / 32, CC / 32, BB), 256>>>(x, XT);
    wpre_kernel<<<dim3(48, 64), 256>>>(E, wp, WT);

    cudaFuncSetAttribute(mma_gemm, cudaFuncAttributeMaxDynamicSharedMemorySize, GEMM_SMEM);
    dim3 ggrid(NN / 128, (BB * CC) / 128);
    mma_gemm<<<ggrid, 256, GEMM_SMEM>>>(A, XT, y1h, nullptr, 1);
    trhh_kernel<<<dim3(NN / 32, CC / 32, BB), 256>>>(y1h, y1T);
    mma_gemm<<<ggrid, 256, GEMM_SMEM>>>(A, y1T, y2h, x, 2);

    cudaFuncSetAttribute(out4_kernel, cudaFuncAttributeMaxDynamicSharedMemorySize, OUT4_SMEM);
    out4_kernel<<<NN, 128, OUT4_SMEM>>>(x, E, WT, bp, out);
}

// round 9
// speedup vs baseline: 1.1473x; 1.0763x over previous
#include <cuda_runtime.h>
#include <cuda_fp16.h>
#include <cstdint>

#define NN 2048
#define EMBD 16
#define BB 64
#define CC 64

// Scratch (no cudaMalloc allowed)
static __device__ __half g_A[NN * NN];            // adjacency, fp16
static __device__ __half g_xh[BB * NN * CC];      // fp16(x), [b][m][c]
static __device__ __half g_y1h[BB * NN * CC];     // A@X, fp16, [b][n][c]
static __device__ __half g_y2h[BB * NN * CC];     // 2A@y1 - X, fp16, [b][n][c]
static __device__ __half g_WT[NN * 3 * CC * CC];  // per-node weights [n][o][kk], fp16

// ---------------------------------------------------------------------------
__device__ __forceinline__ uint32_t smem_u32(const void* p) {
    uint32_t a;
    asm("{ .reg .u64 t; cvta.to.shared.u64 t, %1; cvt.u32.u64 %0, t; }" : "=r"(a) : "l"(p));
    return a;
}
__device__ __forceinline__ void cp16(uint32_t dst, const void* src) {
    asm volatile("cp.async.cg.shared.global [%0], [%1], 16;" :: "r"(dst), "l"(src));
}
__device__ __forceinline__ void cp_commit() { asm volatile("cp.async.commit_group;"); }
__device__ __forceinline__ void cp_wait2() { asm volatile("cp.async.wait_group 2;" ::: "memory"); }

__device__ __forceinline__ void mma16(float* d, const uint32_t* a, uint32_t b0, uint32_t b1) {
    asm volatile(
        "mma.sync.aligned.m16n8k16.row.col.f32.f16.f16.f32 "
        "{%0,%1,%2,%3}, {%4,%5,%6,%7}, {%8,%9}, {%0,%1,%2,%3};"
        : "+f"(d[0]), "+f"(d[1]), "+f"(d[2]), "+f"(d[3])
        : "r"(a[0]), "r"(a[1]), "r"(a[2]), "r"(a[3]), "r"(b0), "r"(b1));
}
__device__ __forceinline__ void ldsm4(uint32_t* r, uint32_t addr) {
    asm volatile("ldmatrix.sync.aligned.m8n8.x4.shared.b16 {%0,%1,%2,%3}, [%4];"
                 : "=r"(r[0]), "=r"(r[1]), "=r"(r[2]), "=r"(r[3]) : "r"(addr));
}
__device__ __forceinline__ void ldsm4t(uint32_t* r, uint32_t addr) {
    asm volatile("ldmatrix.sync.aligned.m8n8.x4.trans.shared.b16 {%0,%1,%2,%3}, [%4];"
                 : "=r"(r[0]), "=r"(r[1]), "=r"(r[2]), "=r"(r[3]) : "r"(addr));
}

// ---------------------------------------------------------------------------
// K0: A[r,:] = fp16(softmax(relu(E[r] . E[j]))), 4 rows per block.
// ---------------------------------------------------------------------------
#define SR 4
__global__ __launch_bounds__(256) void supports_kernel(const float* __restrict__ E,
                                                       __half* __restrict__ A) {
    extern __shared__ float zs[];               // SR * NN
    __shared__ float red[SR][8];
    __shared__ float en[SR][EMBD];
    int row0 = blockIdx.x * SR;
    int tid = threadIdx.x;
    if (tid < SR * EMBD) en[tid >> 4][tid & 15] = E[row0 * EMBD + tid];
    __syncthreads();

    float er[SR][EMBD];
#pragma unroll
    for (int r = 0; r < SR; r++)
#pragma unroll
        for (int d = 0; d < EMBD; d++) er[r][d] = en[r][d];

    float lsum[SR] = {0.f, 0.f, 0.f, 0.f};
    for (int j = tid; j < NN; j += 256) {
        const float4* ej = reinterpret_cast<const float4*>(E + (size_t)j * EMBD);
        float4 v0 = ej[0], v1 = ej[1], v2 = ej[2], v3 = ej[3];
#pragma unroll
        for (int r = 0; r < SR; r++) {
            float s = 0.f;
            s = fmaf(er[r][0], v0.x, s);  s = fmaf(er[r][1], v0.y, s);
            s = fmaf(er[r][2], v0.z, s);  s = fmaf(er[r][3], v0.w, s);
            s = fmaf(er[r][4], v1.x, s);  s = fmaf(er[r][5], v1.y, s);
            s = fmaf(er[r][6], v1.z, s);  s = fmaf(er[r][7], v1.w, s);
            s = fmaf(er[r][8], v2.x, s);  s = fmaf(er[r][9], v2.y, s);
            s = fmaf(er[r][10], v2.z, s); s = fmaf(er[r][11], v2.w, s);
            s = fmaf(er[r][12], v3.x, s); s = fmaf(er[r][13], v3.y, s);
            s = fmaf(er[r][14], v3.z, s); s = fmaf(er[r][15], v3.w, s);
            float e = __expf(fmaxf(s, 0.f));
            zs[r * NN + j] = e;
            lsum[r] += e;
        }
    }
#pragma unroll
    for (int r = 0; r < SR; r++) {
#pragma unroll
        for (int o = 16; o > 0; o >>= 1) lsum[r] += __shfl_xor_sync(~0u, lsum[r], o);
        if ((tid & 31) == 0) red[r][tid >> 5] = lsum[r];
    }
    __syncthreads();
    float inv[SR];
#pragma unroll
    for (int r = 0; r < SR; r++) {
        float s = 0.f;
#pragma unroll
        for (int w = 0; w < 8; w++) s += red[r][w];
        inv[r] = 1.f / s;
    }
    for (int j = tid; j < NN; j += 256) {
#pragma unroll
        for (int r = 0; r < SR; r++)
            A[(size_t)(row0 + r) * NN + j] = __float2half_rn(zs[r * NN + j] * inv[r]);
    }
}

// ---------------------------------------------------------------------------
// xh: fp16 convert of x (same layout). 8 elems/thread.
// ---------------------------------------------------------------------------
__global__ __launch_bounds__(256) void xh_kernel(const float* __restrict__ X,
                                                 __half* __restrict__ D) {
    size_t i = ((size_t)blockIdx.x * 256 + threadIdx.x) * 8;
    float4 a = *reinterpret_cast<const float4*>(X + i);
    float4 b = *reinterpret_cast<const float4*>(X + i + 4);
    union { uint4 u; __half2 h[4]; } o;
    o.h[0] = __floats2half2_rn(a.x, a.y);
    o.h[1] = __floats2half2_rn(a.z, a.w);
    o.h[2] = __floats2half2_rn(b.x, b.y);
    o.h[3] = __floats2half2_rn(b.z, b.w);
    *reinterpret_cast<uint4*>(D + i) = o.u;
}

// ---------------------------------------------------------------------------
// W precompute (transposed, fp16): WT[n][o*192 + kk] = fp16(sum_d E[n,d]*wp[d, kk*64+o])
// ---------------------------------------------------------------------------
__global__ __launch_bounds__(256) void wpre_kernel(const float* __restrict__ E,
                                                   const float* __restrict__ wp,
                                                   __half* __restrict__ WT) {
    __shared__ float wps[EMBD][256];
    __shared__ float Es[32][EMBD];
    int k0 = blockIdx.x * 4;
    int idx0 = blockIdx.x * 256;
    int n0 = blockIdx.y * 32;
    int tid = threadIdx.x;
#pragma unroll
    for (int i = 0; i < 4; i++) {
        int f = tid + i * 256;
        int d = f >> 6, c4 = f & 63;
        float4 v = *reinterpret_cast<const float4*>(wp + (size_t)d * 12288 + idx0 + c4 * 4);
        *reinterpret_cast<float4*>(&wps[d][c4 * 4]) = v;
    }
    if (tid < 128) {
        int nl = tid >> 2, dq = tid & 3;
        float4 v = *reinterpret_cast<const float4*>(E + (n0 + nl) * EMBD + dq * 4);
        *reinterpret_cast<float4*>(&Es[nl][dq * 4]) = v;
    }
    __syncthreads();

    int o = tid & 63;
    int g = tid >> 6;
    float wc[4][EMBD];
#pragma unroll
    for (int dk = 0; dk < 4; dk++)
#pragma unroll
        for (int d = 0; d < EMBD; d++) wc[dk][d] = wps[d][dk * 64 + o];

#pragma unroll
    for (int q = 0; q < 8; q++) {
        int nl = g * 8 + q;
        float s[4] = {0.f, 0.f, 0.f, 0.f};
#pragma unroll
        for (int d = 0; d < EMBD; d++) {
            float e = Es[nl][d];
#pragma unroll
            for (int dk = 0; dk < 4; dk++) s[dk] = fmaf(e, wc[dk][d], s[dk]);
        }
        __half2 h01 = __halves2half2(__float2half_rn(s[0]), __float2half_rn(s[1]));
        __half2 h23 = __halves2half2(__float2half_rn(s[2]), __float2half_rn(s[3]));
        __half2* dst = reinterpret_cast<__half2*>(
            WT + (size_t)(n0 + nl) * 12288 + o * 192 + k0);
        dst[0] = h01;
        dst[1] = h23;
    }
}

// ---------------------------------------------------------------------------
// fp16 mma.sync GEMM, B row-major via ldmatrix.trans.
// D[n, bc] = sum_m A[n,m] * B[b][m][c]  (bc = b*64+c)
// CTA 128x128xK32, 8 warps (2m x 4n), warp tile 64x32, 4-stage cp.async.
// mode 1: Yh = acc.  mode 2: Yh = 2*acc - Xsub.
// Stage: A 8KB (rows 64B, xor-swz), B 8KB (64 rows [2b x 32m] of 128B, xor-swz).
// ---------------------------------------------------------------------------
#define GEMM_SMEM 65536

__global__ __launch_bounds__(256, 2) void mma_gemm(const __half* __restrict__ Ag,
                                                   const __half* __restrict__ Bh,
                                                   __half* __restrict__ Yh,
                                                   const float* __restrict__ Xsub,
                                                   int mode) {
    extern __shared__ char smc[];
    uint32_t sb = smem_u32(smc);

    int tid = threadIdx.x;
    int wid = tid >> 5;
    int lid = tid & 31;
    int wm = wid & 1;
    int wn = wid >> 1;
    int n0 = blockIdx.x * 128;
    int bc0 = blockIdx.y * 128;
    int b0 = bc0 >> 6;          // 2 b's per block

    const __half* Arow = Ag + (size_t)n0 * NN;

    auto load_tile = [&](int it, int buf) {
        int m0 = it * 32;
        uint32_t ab = sb + buf * 16384;
        uint32_t bb = ab + 8192;
        // A: 128 rows x 64B (4 chunks)
#pragma unroll
        for (int i = 0; i < 2; i++) {
            int idx = tid + i * 256;
            int row = idx >> 2, c = idx & 3;
            int pc = c ^ ((row >> 1) & 3);
            cp16(ab + row * 64 + pc * 16, Arow + (size_t)row * NN + m0 + c * 8);
        }
        // B: 64 rows (2b x 32m) x 128B (8 chunks)
#pragma unroll
        for (int i = 0; i < 2; i++) {
            int idx = tid + i * 256;
            int row = idx >> 3, cc = idx & 7;
            int bloc = row >> 5, m = row & 31;
            int pc = cc ^ (m & 7);
            cp16(bb + row * 128 + pc * 16,
                 Bh + ((size_t)(b0 + bloc) * NN + m0 + m) * CC + cc * 8);
        }
        cp_commit();
    };

    int g = lid >> 3, lrw = lid & 7;
    // A fragment addressing (unchanged)
    int xorv = (lrw >> 1) & 3;
    int chHalf = g >> 1;
    uint32_t aBase = (uint32_t)(wm * 64 + (g & 1) * 8 + lrw) * 64;
    // B fragment addressing (trans): warp covers 1 b, 32 c
    int bloc_w = wn >> 1;
    int warp_c = (wn & 1) * 32;
    uint32_t bRowRel = (uint32_t)(bloc_w * 32 + (g & 1) * 8 + lrw) * 128;
    int chunk0 = (warp_c >> 3) + (g >> 1);          // + t*2 per n-tile
    uint32_t bSw0 = (uint32_t)((chunk0 + 0) ^ lrw) * 16;
    uint32_t bSw1 = (uint32_t)((chunk0 + 2) ^ lrw) * 16;

    float acc[4][4][4];
#pragma unroll
    for (int mt = 0; mt < 4; mt++)
#pragma unroll
        for (int nt = 0; nt < 4; nt++)
#pragma unroll
            for (int q = 0; q < 4; q++) acc[mt][nt][q] = 0.f;

    load_tile(0, 0);
    load_tile(1, 1);
    load_tile(2, 2);

    const int ITERS = NN / 32;
    for (int it = 0; it < ITERS; it++) {
        int buf = it & 3;
        cp_wait2();
        __syncthreads();
        uint32_t aB = sb + buf * 16384 + aBase;
        uint32_t bB = sb + buf * 16384 + 8192 + bRowRel;

        uint32_t af[4][4], bf[2][4];
        // ks = 0
        {
            uint32_t pc = (uint32_t)((0 + chHalf) ^ xorv) * 16;
#pragma unroll
            for (int mt = 0; mt < 4; mt++) ldsm4(af[mt], aB + mt * 1024 + pc);
            ldsm4t(bf[0], bB + bSw0);
            ldsm4t(bf[1], bB + bSw1);
        }
        if (it + 3 < ITERS) load_tile(it + 3, (it + 3) & 3); else cp_commit();
#pragma unroll
        for (int mt = 0; mt < 4; mt++) {
            mma16(acc[mt][0], af[mt], bf[0][0], bf[0][1]);
            mma16(acc[mt][1], af[mt], bf[0][2], bf[0][3]);
            mma16(acc[mt][2], af[mt], bf[1][0], bf[1][1]);
            mma16(acc[mt][3], af[mt], bf[1][2], bf[1][3]);
        }
        // ks = 1
        {
            uint32_t pc = (uint32_t)((2 + chHalf) ^ xorv) * 16;
#pragma unroll
            for (int mt = 0; mt < 4; mt++) ldsm4(af[mt], aB + mt * 1024 + pc);
            ldsm4t(bf[0], bB + 2048 + bSw0);
            ldsm4t(bf[1], bB + 2048 + bSw1);
        }
#pragma unroll
        for (int mt = 0; mt < 4; mt++) {
            mma16(acc[mt][0], af[mt], bf[0][0], bf[0][1]);
            mma16(acc[mt][1], af[mt], bf[0][2], bf[0][3]);
            mma16(acc[mt][2], af[mt], bf[1][0], bf[1][1]);
            mma16(acc[mt][3], af[mt], bf[1][2], bf[1][3]);
        }
    }

    int lr = lid >> 2, lc = lid & 3;
#pragma unroll
    for (int mt = 0; mt < 4; mt++) {
#pragma unroll
        for (int nt = 0; nt < 4; nt++) {
            int n = n0 + wm * 64 + mt * 16 + lr;
            int bc = bc0 + wn * 32 + (nt >> 1) * 16 + (nt & 1) * 8 + lc * 2;
            int b = bc >> 6, c = bc & 63;
            float2 v0 = make_float2(acc[mt][nt][0], acc[mt][nt][1]);
            float2 v1 = make_float2(acc[mt][nt][2], acc[mt][nt][3]);
            if (mode == 2) {
                const float2 x0 = *reinterpret_cast<const float2*>(
                    Xsub + ((size_t)b * NN + n) * CC + c);
                const float2 x1 = *reinterpret_cast<const float2*>(
                    Xsub + ((size_t)b * NN + n + 8) * CC + c);
                v0.x = fmaf(2.f, v0.x, -x0.x);
                v0.y = fmaf(2.f, v0.y, -x0.y);
                v1.x = fmaf(2.f, v1.x, -x1.x);
                v1.y = fmaf(2.f, v1.y, -x1.y);
            }
            *reinterpret_cast<__half2*>(Yh + ((size_t)b * NN + n) * CC + c) =
                __floats2half2_rn(v0.x, v0.y);
            *reinterpret_cast<__half2*>(Yh + ((size_t)b * NN + n + 8) * CC + c) =
                __floats2half2_rn(v1.x, v1.y);
        }
    }
}

// ---------------------------------------------------------------------------
// out4: per-node fp16 tensor-core contraction. One block (128 thr, 4 warps) per n.
//   D[64 b, 64 o] = XG[64 b, 192 kk] @ WT[64 o, 192 kk]^T  + bias (fp32)
// ---------------------------------------------------------------------------
#define HSTR 200
#define OUT4_SMEM ((64 * HSTR * 2) * 2 + 64 * 4)
__global__ __launch_bounds__(128) void out4_kernel(const float* __restrict__ E,
                                                   const __half* __restrict__ WTg,
                                                   const float* __restrict__ bp,
                                                   float* __restrict__ OUT) {
    extern __shared__ char smc[];
    __half* XGs = reinterpret_cast<__half*>(smc);            // 64 * 200 halfs
    __half* WTs = XGs + 64 * HSTR;                           // 64 * 200 halfs
    float* bs = reinterpret_cast<float*>(smc + 64 * HSTR * 2 * 2);
    __shared__ float en[EMBD];

    int n = blockIdx.x;
    int tid = threadIdx.x;
    int wid = tid >> 5;
    int lid = tid & 31;
    if (tid < EMBD) en[tid] = E[n * EMBD + tid];
    __syncthreads();

    // XG staging: 3 fp16 sources, uint4 copies (8 halfs)
    const __half* srcs[3] = {g_xh, g_y1h, g_y2h};
#pragma unroll
    for (int k = 0; k < 3; k++) {
        const __half* src = srcs[k];
#pragma unroll
        for (int rep = 0; rep < 4; rep++) {
            int c8 = tid + rep * 128;           // 0..511: b = c8>>3, i8 = c8&7
            int b = c8 >> 3, i8 = c8 & 7;
            uint4 v = *reinterpret_cast<const uint4*>(
                src + ((size_t)b * NN + n) * CC + i8 * 8);
            *reinterpret_cast<uint4*>(&XGs[b * HSTR + k * 64 + i8 * 8]) = v;
        }
    }
    // WT[n]: 12288 halfs, remap stride 192 -> 200
    {
        const uint4* src = reinterpret_cast<const uint4*>(WTg + (size_t)n * 12288);
#pragma unroll
        for (int rep = 0; rep < 12; rep++) {
            int c8 = tid + rep * 128;
            int idx = c8 * 8;
            int o = idx / 192, kk = idx - o * 192;
            *reinterpret_cast<uint4*>(&WTs[o * HSTR + kk]) = src[c8];
        }
    }
    if (tid < 64) {
        float s = 0.f;
#pragma unroll
        for (int d = 0; d < EMBD; d++) s = fmaf(en[d], bp[d * 64 + tid], s);
        bs[tid] = s;
    }
    __syncthreads();

    int lm = lid >> 3, lrw = lid & 7;
    uint32_t aLane = smem_u32(XGs) + (uint32_t)(wid * 16 + (lm & 1) * 8 + lrw) * (HSTR * 2) +
                     (lm >> 1) * 16;
    uint32_t bLane = smem_u32(WTs) + (uint32_t)((lm & 1) * 8 + lrw) * (HSTR * 2) +
                     (lm >> 1) * 16;

    float acc[8][4];
#pragma unroll
    for (int nt = 0; nt < 8; nt++)
#pragma unroll
        for (int q = 0; q < 4; q++) acc[nt][q] = 0.f;

#pragma unroll
    for (int kt = 0; kt < 12; kt++) {
        uint32_t koff = (uint32_t)kt * 32;
        uint32_t af[4];
        ldsm4(af, aLane + koff);
#pragma unroll
        for (int g = 0; g < 4; g++) {
            uint32_t bf[4];
            ldsm4(bf, bLane + g * 16 * (HSTR * 2) + koff);
            mma16(acc[g * 2 + 0], af, bf[0], bf[2]);
            mma16(acc[g * 2 + 1], af, bf[1], bf[3]);
        }
    }

    int lr = lid >> 2, lc = lid & 3;
    int b0 = wid * 16 + lr;
#pragma unroll
    for (int nt = 0; nt < 8; nt++) {
        int o = nt * 8 + lc * 2;
        float2 bias = *reinterpret_cast<const float2*>(&bs[o]);
        float2 v0 = make_float2(acc[nt][0] + bias.x, acc[nt][1] + bias.y);
        float2 v1 = make_float2(acc[nt][2] + bias.x, acc[nt][3] + bias.y);
        *reinterpret_cast<float2*>(OUT + ((size_t)b0 * NN + n) * CC + o) = v0;
        *reinterpret_cast<float2*>(OUT + ((size_t)(b0 + 8) * NN + n) * CC + o) = v1;
    }
}

// ---------------------------------------------------------------------------
extern "C" void kernel_launch(void* const* d_in, const int* in_sizes, int n_in,
                              void* d_out, int out_size) {
    const float *x = nullptr, *E = nullptr, *wp = nullptr, *bp = nullptr;
    for (int i = 0; i < n_in; i++) {
        switch (in_sizes[i]) {
            case BB * NN * CC:       x = (const float*)d_in[i]; break;
            case NN * EMBD:          E = (const float*)d_in[i]; break;
            case EMBD * 3 * CC * CC: wp = (const float*)d_in[i]; break;
            case EMBD * CC:          bp = (const float*)d_in[i]; break;
        }
    }
    float* out = (float*)d_out;

    __half *A, *xh, *y1h, *y2h, *WT;
    cudaGetSymbolAddress((void**)&A, g_A);
    cudaGetSymbolAddress((void**)&xh, g_xh);
    cudaGetSymbolAddress((void**)&y1h, g_y1h);
    cudaGetSymbolAddress((void**)&y2h, g_y2h);
    cudaGetSymbolAddress((void**)&WT, g_WT);

    int ssm = SR * NN * (int)sizeof(float);
    cudaFuncSetAttribute(supports_kernel, cudaFuncAttributeMaxDynamicSharedMemorySize, ssm);
    supports_kernel<<<NN / SR, 256, ssm>>>(E, A);
    xh_kernel<<<(BB * NN * CC) / (256 * 8), 256>>>(x, xh);
    wpre_kernel<<<dim3(48, 64), 256>>>(E, wp, WT);

    cudaFuncSetAttribute(mma_gemm, cudaFuncAttributeMaxDynamicSharedMemorySize, GEMM_SMEM);
    dim3 ggrid(NN / 128, (BB * CC) / 128);
    mma_gemm<<<ggrid, 256, GEMM_SMEM>>>(A, xh, y1h, nullptr, 1);
    mma_gemm<<<ggrid, 256, GEMM_SMEM>>>(A, y1h, y2h, x, 2);

    cudaFuncSetAttribute(out4_kernel, cudaFuncAttributeMaxDynamicSharedMemorySize, OUT4_SMEM);
    out4_kernel<<<NN, 128, OUT4_SMEM>>>(E, WT, bp, out);
}

// round 10
// speedup vs baseline: 1.2573x; 1.0959x over previous
#include <cuda_runtime.h>
#include <cuda_fp16.h>
#include <cstdint>

#define NN 2048
#define EMBD 16
#define BB 64
#define CC 64

// Scratch (no cudaMalloc allowed)
static __device__ __half g_A[NN * NN];            // adjacency, fp16
static __device__ __half g_xh[BB * NN * CC];      // fp16(x), [b][m][c]
static __device__ __half g_y1h[BB * NN * CC];     // A@X, fp16, [b][n][c]
static __device__ __half g_y2h[BB * NN * CC];     // 2A@y1 - X, fp16, [b][n][c]
static __device__ __half g_WT[NN * 3 * CC * CC];  // per-node weights [n][o][kk], fp16

// ---------------------------------------------------------------------------
__device__ __forceinline__ uint32_t smem_u32(const void* p) {
    uint32_t a;
    asm("{ .reg .u64 t; cvta.to.shared.u64 t, %1; cvt.u32.u64 %0, t; }" : "=r"(a) : "l"(p));
    return a;
}
__device__ __forceinline__ void cp16(uint32_t dst, const void* src) {
    asm volatile("cp.async.cg.shared.global [%0], [%1], 16;" :: "r"(dst), "l"(src));
}
__device__ __forceinline__ void cp_commit() { asm volatile("cp.async.commit_group;"); }
__device__ __forceinline__ void cp_wait1() { asm volatile("cp.async.wait_group 1;" ::: "memory"); }
__device__ __forceinline__ void cp_wait0() { asm volatile("cp.async.wait_group 0;" ::: "memory"); }

__device__ __forceinline__ void mma16(float* d, const uint32_t* a, uint32_t b0, uint32_t b1) {
    asm volatile(
        "mma.sync.aligned.m16n8k16.row.col.f32.f16.f16.f32 "
        "{%0,%1,%2,%3}, {%4,%5,%6,%7}, {%8,%9}, {%0,%1,%2,%3};"
        : "+f"(d[0]), "+f"(d[1]), "+f"(d[2]), "+f"(d[3])
        : "r"(a[0]), "r"(a[1]), "r"(a[2]), "r"(a[3]), "r"(b0), "r"(b1));
}
__device__ __forceinline__ void ldsm4(uint32_t* r, uint32_t addr) {
    asm volatile("ldmatrix.sync.aligned.m8n8.x4.shared.b16 {%0,%1,%2,%3}, [%4];"
                 : "=r"(r[0]), "=r"(r[1]), "=r"(r[2]), "=r"(r[3]) : "r"(addr));
}
__device__ __forceinline__ void ldsm4t(uint32_t* r, uint32_t addr) {
    asm volatile("ldmatrix.sync.aligned.m8n8.x4.trans.shared.b16 {%0,%1,%2,%3}, [%4];"
                 : "=r"(r[0]), "=r"(r[1]), "=r"(r[2]), "=r"(r[3]) : "r"(addr));
}

// ---------------------------------------------------------------------------
// K0: A[r,:] = fp16(softmax(relu(E[r] . E[j]))), 4 rows per block.
// ---------------------------------------------------------------------------
#define SR 4
__global__ __launch_bounds__(256) void supports_kernel(const float* __restrict__ E,
                                                       __half* __restrict__ A) {
    extern __shared__ float zs[];               // SR * NN
    __shared__ float red[SR][8];
    __shared__ float en[SR][EMBD];
    int row0 = blockIdx.x * SR;
    int tid = threadIdx.x;
    if (tid < SR * EMBD) en[tid >> 4][tid & 15] = E[row0 * EMBD + tid];
    __syncthreads();

    float er[SR][EMBD];
#pragma unroll
    for (int r = 0; r < SR; r++)
#pragma unroll
        for (int d = 0; d < EMBD; d++) er[r][d] = en[r][d];

    float lsum[SR] = {0.f, 0.f, 0.f, 0.f};
    for (int j = tid; j < NN; j += 256) {
        const float4* ej = reinterpret_cast<const float4*>(E + (size_t)j * EMBD);
        float4 v0 = ej[0], v1 = ej[1], v2 = ej[2], v3 = ej[3];
#pragma unroll
        for (int r = 0; r < SR; r++) {
            float s = 0.f;
            s = fmaf(er[r][0], v0.x, s);  s = fmaf(er[r][1], v0.y, s);
            s = fmaf(er[r][2], v0.z, s);  s = fmaf(er[r][3], v0.w, s);
            s = fmaf(er[r][4], v1.x, s);  s = fmaf(er[r][5], v1.y, s);
            s = fmaf(er[r][6], v1.z, s);  s = fmaf(er[r][7], v1.w, s);
            s = fmaf(er[r][8], v2.x, s);  s = fmaf(er[r][9], v2.y, s);
            s = fmaf(er[r][10], v2.z, s); s = fmaf(er[r][11], v2.w, s);
            s = fmaf(er[r][12], v3.x, s); s = fmaf(er[r][13], v3.y, s);
            s = fmaf(er[r][14], v3.z, s); s = fmaf(er[r][15], v3.w, s);
            float e = __expf(fmaxf(s, 0.f));
            zs[r * NN + j] = e;
            lsum[r] += e;
        }
    }
#pragma unroll
    for (int r = 0; r < SR; r++) {
#pragma unroll
        for (int o = 16; o > 0; o >>= 1) lsum[r] += __shfl_xor_sync(~0u, lsum[r], o);
        if ((tid & 31) == 0) red[r][tid >> 5] = lsum[r];
    }
    __syncthreads();
    float inv[SR];
#pragma unroll
    for (int r = 0; r < SR; r++) {
        float s = 0.f;
#pragma unroll
        for (int w = 0; w < 8; w++) s += red[r][w];
        inv[r] = 1.f / s;
    }
    for (int j = tid; j < NN; j += 256) {
#pragma unroll
        for (int r = 0; r < SR; r++)
            A[(size_t)(row0 + r) * NN + j] = __float2half_rn(zs[r * NN + j] * inv[r]);
    }
}

// ---------------------------------------------------------------------------
// xh: fp16 convert of x (same layout). 8 elems/thread.
// ---------------------------------------------------------------------------
__global__ __launch_bounds__(256) void xh_kernel(const float* __restrict__ X,
                                                 __half* __restrict__ D) {
    size_t i = ((size_t)blockIdx.x * 256 + threadIdx.x) * 8;
    float4 a = *reinterpret_cast<const float4*>(X + i);
    float4 b = *reinterpret_cast<const float4*>(X + i + 4);
    union { uint4 u; __half2 h[4]; } o;
    o.h[0] = __floats2half2_rn(a.x, a.y);
    o.h[1] = __floats2half2_rn(a.z, a.w);
    o.h[2] = __floats2half2_rn(b.x, b.y);
    o.h[3] = __floats2half2_rn(b.z, b.w);
    *reinterpret_cast<uint4*>(D + i) = o.u;
}

// ---------------------------------------------------------------------------
// W precompute (transposed, fp16): WT[n][o*192 + kk] = fp16(sum_d E[n,d]*wp[d, kk*64+o])
// ---------------------------------------------------------------------------
__global__ __launch_bounds__(256) void wpre_kernel(const float* __restrict__ E,
                                                   const float* __restrict__ wp,
                                                   __half* __restrict__ WT) {
    __shared__ float wps[EMBD][256];
    __shared__ float Es[32][EMBD];
    int k0 = blockIdx.x * 4;
    int idx0 = blockIdx.x * 256;
    int n0 = blockIdx.y * 32;
    int tid = threadIdx.x;
#pragma unroll
    for (int i = 0; i < 4; i++) {
        int f = tid + i * 256;
        int d = f >> 6, c4 = f & 63;
        float4 v = *reinterpret_cast<const float4*>(wp + (size_t)d * 12288 + idx0 + c4 * 4);
        *reinterpret_cast<float4*>(&wps[d][c4 * 4]) = v;
    }
    if (tid < 128) {
        int nl = tid >> 2, dq = tid & 3;
        float4 v = *reinterpret_cast<const float4*>(E + (n0 + nl) * EMBD + dq * 4);
        *reinterpret_cast<float4*>(&Es[nl][dq * 4]) = v;
    }
    __syncthreads();

    int o = tid & 63;
    int g = tid >> 6;
    float wc[4][EMBD];
#pragma unroll
    for (int dk = 0; dk < 4; dk++)
#pragma unroll
        for (int d = 0; d < EMBD; d++) wc[dk][d] = wps[d][dk * 64 + o];

#pragma unroll
    for (int q = 0; q < 8; q++) {
        int nl = g * 8 + q;
        float s[4] = {0.f, 0.f, 0.f, 0.f};
#pragma unroll
        for (int d = 0; d < EMBD; d++) {
            float e = Es[nl][d];
#pragma unroll
            for (int dk = 0; dk < 4; dk++) s[dk] = fmaf(e, wc[dk][d], s[dk]);
        }
        __half2 h01 = __halves2half2(__float2half_rn(s[0]), __float2half_rn(s[1]));
        __half2 h23 = __halves2half2(__float2half_rn(s[2]), __float2half_rn(s[3]));
        __half2* dst = reinterpret_cast<__half2*>(
            WT + (size_t)(n0 + nl) * 12288 + o * 192 + k0);
        dst[0] = h01;
        dst[1] = h23;
    }
}

// ---------------------------------------------------------------------------
// fp16 mma.sync GEMM, B row-major via ldmatrix.trans, K=64 stages.
// D[n, bc] = sum_m A[n,m] * B[b][m][c]  (bc = b*64+c)
// CTA 128x128xK64, 8 warps (2m x 4n), warp tile 64x32, 3-stage cp.async.
// Stage: A 16KB (128 rows x 128B, xor-swz pc=c^(row&7)),
//        B 16KB (128 rows [2b x 64m] x 128B, xor-swz pc=c^(m&7)).
// mode 1: Yh = acc.  mode 2: Yh = 2*acc - Xh.
// ---------------------------------------------------------------------------
#define GEMM_SMEM 98304  // 3 stages x 32KB

__global__ __launch_bounds__(256, 2) void mma_gemm(const __half* __restrict__ Ag,
                                                   const __half* __restrict__ Bh,
                                                   __half* __restrict__ Yh,
                                                   const __half* __restrict__ Xh,
                                                   int mode) {
    extern __shared__ char smc[];
    uint32_t sb = smem_u32(smc);

    int tid = threadIdx.x;
    int wid = tid >> 5;
    int lid = tid & 31;
    int wm = wid & 1;
    int wn = wid >> 1;
    int n0 = blockIdx.x * 128;
    int bc0 = blockIdx.y * 128;
    int b0 = bc0 >> 6;          // 2 b's per block

    const __half* Arow = Ag + (size_t)n0 * NN;

    auto load_tile = [&](int it, int buf) {
        int m0 = it * 64;
        uint32_t ab = sb + buf * 32768;
        uint32_t bb = ab + 16384;
        // A: 128 rows x 128B (8 chunks)
#pragma unroll
        for (int i = 0; i < 4; i++) {
            int idx = tid + i * 256;
            int row = idx >> 3, c = idx & 7;
            int pc = c ^ (row & 7);
            cp16(ab + row * 128 + pc * 16, Arow + (size_t)row * NN + m0 + c * 8);
        }
        // B: 128 rows (2b x 64m) x 128B (8 chunks)
#pragma unroll
        for (int i = 0; i < 4; i++) {
            int idx = tid + i * 256;
            int row = idx >> 3, c = idx & 7;
            int bloc = row >> 6, m = row & 63;
            int pc = c ^ (m & 7);
            cp16(bb + row * 128 + pc * 16,
                 Bh + ((size_t)(b0 + bloc) * NN + m0 + m) * CC + c * 8);
        }
        cp_commit();
    };

    int g = lid >> 3, lrw = lid & 7;
    int chHalf = g >> 1;
    // A fragment: rows = wm*64 + mt*16 + (g&1)*8 + lrw, 128B rows
    uint32_t aBase = (uint32_t)(wm * 64 + (g & 1) * 8 + lrw) * 128;
    // B fragment (trans): warp covers 1 b, 32 c; rows = bloc*64 + m
    int bloc_w = wn >> 1;
    int warp_c = (wn & 1) * 32;
    uint32_t bRowRel = (uint32_t)(bloc_w * 64 + (g & 1) * 8 + lrw) * 128;
    int chunk0 = (warp_c >> 3) + chHalf;
    uint32_t bSw0 = (uint32_t)((chunk0 + 0) ^ lrw) * 16;
    uint32_t bSw1 = (uint32_t)((chunk0 + 2) ^ lrw) * 16;

    float acc[4][4][4];
#pragma unroll
    for (int mt = 0; mt < 4; mt++)
#pragma unroll
        for (int nt = 0; nt < 4; nt++)
#pragma unroll
            for (int q = 0; q < 4; q++) acc[mt][nt][q] = 0.f;

    load_tile(0, 0);
    load_tile(1, 1);

    const int ITERS = NN / 64;
    for (int it = 0; it < ITERS; it++) {
        int buf = it % 3;
        if (it == ITERS - 1) cp_wait0(); else cp_wait1();
        __syncthreads();
        uint32_t aB = sb + buf * 32768 + aBase;
        uint32_t bB = sb + buf * 32768 + 16384 + bRowRel;

#pragma unroll
        for (int ks = 0; ks < 4; ks++) {
            uint32_t af[4][4], bf[2][4];
            uint32_t apc = (uint32_t)((ks * 2 + chHalf) ^ lrw) * 16;
#pragma unroll
            for (int mt = 0; mt < 4; mt++) ldsm4(af[mt], aB + mt * 2048 + apc);
            uint32_t bko = (uint32_t)ks * 2048;   // ks*16 rows * 128B
            ldsm4t(bf[0], bB + bko + bSw0);
            ldsm4t(bf[1], bB + bko + bSw1);
            if (ks == 0) {
                if (it + 2 < ITERS) load_tile(it + 2, (it + 2) % 3);
                else cp_commit();
            }
#pragma unroll
            for (int mt = 0; mt < 4; mt++) {
                mma16(acc[mt][0], af[mt], bf[0][0], bf[0][1]);
                mma16(acc[mt][1], af[mt], bf[0][2], bf[0][3]);
                mma16(acc[mt][2], af[mt], bf[1][0], bf[1][1]);
                mma16(acc[mt][3], af[mt], bf[1][2], bf[1][3]);
            }
        }
    }

    int lr = lid >> 2, lc = lid & 3;
#pragma unroll
    for (int mt = 0; mt < 4; mt++) {
#pragma unroll
        for (int nt = 0; nt < 4; nt++) {
            int n = n0 + wm * 64 + mt * 16 + lr;
            int bc = bc0 + wn * 32 + (nt >> 1) * 16 + (nt & 1) * 8 + lc * 2;
            int b = bc >> 6, c = bc & 63;
            float2 v0 = make_float2(acc[mt][nt][0], acc[mt][nt][1]);
            float2 v1 = make_float2(acc[mt][nt][2], acc[mt][nt][3]);
            if (mode == 2) {
                __half2 xh0 = *reinterpret_cast<const __half2*>(
                    Xh + ((size_t)b * NN + n) * CC + c);
                __half2 xh1 = *reinterpret_cast<const __half2*>(
                    Xh + ((size_t)b * NN + n + 8) * CC + c);
                float2 x0 = __half22float2(xh0);
                float2 x1 = __half22float2(xh1);
                v0.x = fmaf(2.f, v0.x, -x0.x);
                v0.y = fmaf(2.f, v0.y, -x0.y);
                v1.x = fmaf(2.f, v1.x, -x1.x);
                v1.y = fmaf(2.f, v1.y, -x1.y);
            }
            *reinterpret_cast<__half2*>(Yh + ((size_t)b * NN + n) * CC + c) =
                __floats2half2_rn(v0.x, v0.y);
            *reinterpret_cast<__half2*>(Yh + ((size_t)b * NN + n + 8) * CC + c) =
                __floats2half2_rn(v1.x, v1.y);
        }
    }
}

// ---------------------------------------------------------------------------
// out4: per-node fp16 tensor-core contraction. One block (128 thr, 4 warps) per n.
//   D[64 b, 64 o] = XG[64 b, 192 kk] @ WT[64 o, 192 kk]^T  + bias (fp32)
// Staging via cp.async (all 24 x 16B per thread in flight before one wait).
// ---------------------------------------------------------------------------
#define HSTR 200
#define OUT4_SMEM ((64 * HSTR * 2) * 2 + 64 * 4)
__global__ __launch_bounds__(128) void out4_kernel(const float* __restrict__ E,
                                                   const __half* __restrict__ WTg,
                                                   const float* __restrict__ bp,
                                                   float* __restrict__ OUT) {
    extern __shared__ char smc[];
    __half* XGs = reinterpret_cast<__half*>(smc);            // 64 * 200 halfs
    __half* WTs = XGs + 64 * HSTR;                           // 64 * 200 halfs
    float* bs = reinterpret_cast<float*>(smc + 64 * HSTR * 2 * 2);
    __shared__ float en[EMBD];

    int n = blockIdx.x;
    int tid = threadIdx.x;
    int wid = tid >> 5;
    int lid = tid & 31;
    uint32_t xg_s = smem_u32(XGs);
    uint32_t wt_s = smem_u32(WTs);

    // XG staging: 3 fp16 sources via cp.async
    const __half* srcs[3] = {g_xh, g_y1h, g_y2h};
#pragma unroll
    for (int k = 0; k < 3; k++) {
        const __half* src = srcs[k];
#pragma unroll
        for (int rep = 0; rep < 4; rep++) {
            int c8 = tid + rep * 128;           // 0..511: b = c8>>3, i8 = c8&7
            int b = c8 >> 3, i8 = c8 & 7;
            cp16(xg_s + (uint32_t)(b * HSTR + k * 64 + i8 * 8) * 2,
                 src + ((size_t)b * NN + n) * CC + i8 * 8);
        }
    }
    // WT[n]: 12288 halfs, remap stride 192 -> 200
    {
        const __half* src = WTg + (size_t)n * 12288;
#pragma unroll
        for (int rep = 0; rep < 12; rep++) {
            int c8 = tid + rep * 128;
            int idx = c8 * 8;
            int o = idx / 192, kk = idx - o * 192;
            cp16(wt_s + (uint32_t)(o * HSTR + kk) * 2, src + idx);
        }
    }
    cp_commit();

    if (tid < EMBD) en[tid] = E[n * EMBD + tid];
    __syncthreads();
    if (tid < 64) {
        float s = 0.f;
#pragma unroll
        for (int d = 0; d < EMBD; d++) s = fmaf(en[d], bp[d * 64 + tid], s);
        bs[tid] = s;
    }
    cp_wait0();
    __syncthreads();

    int lm = lid >> 3, lrw = lid & 7;
    uint32_t aLane = xg_s + (uint32_t)(wid * 16 + (lm & 1) * 8 + lrw) * (HSTR * 2) +
                     (lm >> 1) * 16;
    uint32_t bLane = wt_s + (uint32_t)((lm & 1) * 8 + lrw) * (HSTR * 2) +
                     (lm >> 1) * 16;

    float acc[8][4];
#pragma unroll
    for (int nt = 0; nt < 8; nt++)
#pragma unroll
        for (int q = 0; q < 4; q++) acc[nt][q] = 0.f;

#pragma unroll
    for (int kt = 0; kt < 12; kt++) {
        uint32_t koff = (uint32_t)kt * 32;
        uint32_t af[4];
        ldsm4(af, aLane + koff);
#pragma unroll
        for (int g = 0; g < 4; g++) {
            uint32_t bf[4];
            ldsm4(bf, bLane + g * 16 * (HSTR * 2) + koff);
            mma16(acc[g * 2 + 0], af, bf[0], bf[2]);
            mma16(acc[g * 2 + 1], af, bf[1], bf[3]);
        }
    }

    int lr = lid >> 2, lc = lid & 3;
    int b0 = wid * 16 + lr;
#pragma unroll
    for (int nt = 0; nt < 8; nt++) {
        int o = nt * 8 + lc * 2;
        float2 bias = *reinterpret_cast<const float2*>(&bs[o]);
        float2 v0 = make_float2(acc[nt][0] + bias.x, acc[nt][1] + bias.y);
        float2 v1 = make_float2(acc[nt][2] + bias.x, acc[nt][3] + bias.y);
        *reinterpret_cast<float2*>(OUT + ((size_t)b0 * NN + n) * CC + o) = v0;
        *reinterpret_cast<float2*>(OUT + ((size_t)(b0 + 8) * NN + n) * CC + o) = v1;
    }
}

// ---------------------------------------------------------------------------
extern "C" void kernel_launch(void* const* d_in, const int* in_sizes, int n_in,
                              void* d_out, int out_size) {
    const float *x = nullptr, *E = nullptr, *wp = nullptr, *bp = nullptr;
    for (int i = 0; i < n_in; i++) {
        switch (in_sizes[i]) {
            case BB * NN * CC:       x = (const float*)d_in[i]; break;
            case NN * EMBD:          E = (const float*)d_in[i]; break;
            case EMBD * 3 * CC * CC: wp = (const float*)d_in[i]; break;
            case EMBD * CC:          bp = (const float*)d_in[i]; break;
        }
    }
    float* out = (float*)d_out;

    __half *A, *xh, *y1h, *y2h, *WT;
    cudaGetSymbolAddress((void**)&A, g_A);
    cudaGetSymbolAddress((void**)&xh, g_xh);
    cudaGetSymbolAddress((void**)&y1h, g_y1h);
    cudaGetSymbolAddress((void**)&y2h, g_y2h);
    cudaGetSymbolAddress((void**)&WT, g_WT);

    int ssm = SR * NN * (int)sizeof(float);
    cudaFuncSetAttribute(supports_kernel, cudaFuncAttributeMaxDynamicSharedMemorySize, ssm);
    supports_kernel<<<NN / SR, 256, ssm>>>(E, A);
    xh_kernel<<<(BB * NN * CC) / (256 * 8), 256>>>(x, xh);
    wpre_kernel<<<dim3(48, 64), 256>>>(E, wp, WT);

    cudaFuncSetAttribute(mma_gemm, cudaFuncAttributeMaxDynamicSharedMemorySize, GEMM_SMEM);
    dim3 ggrid(NN / 128, (BB * CC) / 128);
    mma_gemm<<<ggrid, 256, GEMM_SMEM>>>(A, xh, y1h, nullptr, 1);
    mma_gemm<<<ggrid, 256, GEMM_SMEM>>>(A, y1h, y2h, xh, 2);

    cudaFuncSetAttribute(out4_kernel, cudaFuncAttributeMaxDynamicSharedMemorySize, OUT4_SMEM);
    out4_kernel<<<NN, 128, OUT4_SMEM>>>(E, WT, bp, out);
}